// round 6
// baseline (speedup 1.0000x reference)
#include <cuda_runtime.h>
#include <cstddef>

#define HH   8
#define TQ   2048
#define TT   4096
#define DK   64
#define NB   64
#define NQG    (HH*TQ)     // 16384
#define NUNITS (HH*NB)     // 512
#define GRID_P 296         // 2 CTAs/SM x 148 SMs, persistent + work stealing

typedef unsigned long long ull;

// Per-slot flash partials (no max shift; scores are O(1) so exp is fp32-safe):
//   g_acc[slot][q][64] = exp(s)·V   (unnormalized)
//   g_l  [slot][q]     = sum exp(s)
// g_cnt[q]: readiness counter; second arriver combines and resets it.
__device__ float g_acc[2u * NQG * DK];
__device__ float g_l  [2u * NQG];
__device__ int   g_cnt[NQG];           // zero-init; combiner re-zeros
__device__ int   g_ticket = GRID_P;
__device__ int   g_exit   = 0;

#define FMA2(d,a,b,c) asm("fma.rn.f32x2 %0, %1, %2, %3;" : "=l"(d) : "l"(a), "l"(b), "l"(c))
#define ADD2(d,a,b)   asm("add.rn.f32x2 %0, %1, %2;"     : "=l"(d) : "l"(a), "l"(b))
#define MUL2(d,a,b)   asm("mul.rn.f32x2 %0, %1, %2;"     : "=l"(d) : "l"(a), "l"(b))
#define DUP2(d,x)     asm("mov.b64 %0, {%1,%1};"         : "=l"(d) : "r"(__float_as_uint(x)))
#define PACK2(d,x,y)  asm("mov.b64 %0, {%1,%2};"         : "=l"(d) : "r"(__float_as_uint(x)), "r"(__float_as_uint(y)))

// ---- dynamic SMEM layout (float offsets) ----
#define KS_OFF    0        // K block: 64 rows x 68 floats (pad -> conflict-free)
#define VS_OFF    4352     // V block: same
#define UBUF_OFF  8704     // per-warp 512 floats: 8 staged q rows
#define QLIST_OFF 12800    // 2048 ushort
#define NM_OFF    13824    // nmatch, nextu
#define SMEM_BYTES ((NM_OFF + 2) * 4)   // 55304

__global__ __launch_bounds__(256, 2)
void partial_kernel(const float* __restrict__ q,
                    const float* __restrict__ k,
                    const float* __restrict__ v,
                    const int*   __restrict__ idx,
                    float*       __restrict__ out)
{
    extern __shared__ float sm[];
    float* ks = sm + KS_OFF;
    float* vs = sm + VS_OFF;
    unsigned short* qlist = (unsigned short*)(sm + QLIST_OFF);
    int* nmatch = (int*)(sm + NM_OFF);
    int* nextu  = nmatch + 1;

    const int tid  = threadIdx.x;
    const int warp = tid >> 5;
    const int lane = tid & 31;
    float* ubuf = sm + UBUF_OFF + warp * 512;

    int u = blockIdx.x;
    while (u < NUNITS) {
        const int hh = u >> 6, bl = u & 63;
        if (tid == 0) *nmatch = 0;

        // ---- stage K/V block (64x64 f32) into padded SMEM ----
        const float4* kg = (const float4*)(k + ((size_t)hh * TT + (size_t)bl * 64) * DK);
        const float4* vg = (const float4*)(v + ((size_t)hh * TT + (size_t)bl * 64) * DK);
        float4* ks4 = (float4*)ks;
        float4* vs4 = (float4*)vs;
        #pragma unroll
        for (int i = tid; i < 1024; i += 256) {
            int row = i >> 4, c = i & 15;
            ks4[row * 17 + c] = kg[i];
            vs4[row * 17 + c] = vg[i];
        }
        __syncthreads();

        // ---- scan top2 list; warp-aggregated append ----
        const int2* idxh = (const int2*)(idx + (size_t)hh * TQ * 2);
        #pragma unroll
        for (int qq = tid; qq < TQ; qq += 256) {
            int2 t2 = idxh[qq];
            int mk = (t2.x == bl ? 1 : 0) | (t2.y == bl ? 2 : 0);
            unsigned bal = __ballot_sync(0xFFFFFFFFu, mk != 0);
            if (mk) {
                int leader = __ffs(bal) - 1;
                int base;
                if (lane == leader) base = atomicAdd(nmatch, __popc(bal));
                base = __shfl_sync(bal, base, leader);
                int pos = base + __popc(bal & ((1u << lane) - 1u));
                qlist[pos] = (unsigned short)(qq | (mk << 12));
            }
        }
        __syncthreads();
        const int n = *nmatch;

        // ---- warp-tiles of 8 queries ----
        for (int base = warp * 8; base < n; base += 64) {
            const int nt = min(8, n - base);
            int qgr[8], mkr[8];
            #pragma unroll
            for (int r = 0; r < 8; r++) {
                int e = base + ((r < nt) ? r : 0);
                unsigned short ent = qlist[e];
                qgr[r] = hh * TQ + (ent & 0x0FFF);
                mkr[r] = (r < nt) ? (ent >> 12) : 0;
            }

            __syncwarp();   // prior tile's ubuf reads done
            #pragma unroll
            for (int r = 0; r < 8; r++) {
                float2 qv = ((const float2*)(q + (size_t)qgr[r] * DK))[lane];
                ((float2*)(ubuf + r * 64))[lane] = qv;
            }
            __syncwarp();

            // ---- QK: lane owns keys {lane, lane+32}; f32x2 along dk ----
            ull sA[8], sB[8];
            #pragma unroll
            for (int r = 0; r < 8; r++) { sA[r] = 0ull; sB[r] = 0ull; }
            {
                const ulonglong2* ka4 = (const ulonglong2*)(ks + lane * 68);
                const ulonglong2* kb4 = (const ulonglong2*)(ks + (lane + 32) * 68);
                #pragma unroll
                for (int i = 0; i < 16; i++) {
                    ulonglong2 ka = ka4[i];
                    ulonglong2 kb = kb4[i];
                    #pragma unroll
                    for (int r = 0; r < 8; r++) {
                        ulonglong2 qv = ((const ulonglong2*)(ubuf + r * 64))[i];
                        FMA2(sA[r], qv.x, ka.x, sA[r]);
                        FMA2(sA[r], qv.y, ka.y, sA[r]);
                        FMA2(sB[r], qv.x, kb.x, sB[r]);
                        FMA2(sB[r], qv.y, kb.y, sB[r]);
                    }
                }
            }

            // ---- exp + l reduction (no max shift) ----
            float e0r[8], e1r[8], lv[8];
            #pragma unroll
            for (int r = 0; r < 8; r++) {
                unsigned lo, hi;
                asm("mov.b64 {%0,%1}, %2;" : "=r"(lo), "=r"(hi) : "l"(sA[r]));
                float s0 = (__uint_as_float(lo) + __uint_as_float(hi)) * 0.125f;
                asm("mov.b64 {%0,%1}, %2;" : "=r"(lo), "=r"(hi) : "l"(sB[r]));
                float s1 = (__uint_as_float(lo) + __uint_as_float(hi)) * 0.125f;
                e0r[r] = __expf(s0);
                e1r[r] = __expf(s1);
                float l = e0r[r] + e1r[r];
                #pragma unroll
                for (int o = 16; o; o >>= 1) l += __shfl_xor_sync(0xFFFFFFFFu, l, o);
                lv[r] = l;
            }

            // ---- PV via register shuffles: lane owns dims {2l, 2l+1} ----
            ull acc[8];
            #pragma unroll
            for (int r = 0; r < 8; r++) acc[r] = 0ull;
            {
                const ull* vr = (const ull*)vs;   // row j at 34*j ull, lane pair +lane
                #pragma unroll 8
                for (int j = 0; j < 32; j++) {
                    ull v2a = vr[j * 34 + lane];
                    ull v2b = vr[(j + 32) * 34 + lane];
                    #pragma unroll
                    for (int r = 0; r < 8; r++) {
                        float p0 = __shfl_sync(0xFFFFFFFFu, e0r[r], j);
                        float p1 = __shfl_sync(0xFFFFFFFFu, e1r[r], j);
                        ull d0, d1;
                        DUP2(d0, p0);
                        DUP2(d1, p1);
                        FMA2(acc[r], d0, v2a, acc[r]);
                        FMA2(acc[r], d1, v2b, acc[r]);
                    }
                }
            }

            // ---- finish: write slot, second arriver combines inline ----
            #pragma unroll
            for (int r = 0; r < 8; r++) {
                if (!mkr[r]) continue;
                const int qg = qgr[r];
                if (mkr[r] == 3) {
                    // dup block: softmax over duplicated keys == acc/l
                    ull iv, o2;
                    DUP2(iv, 1.0f / lv[r]);
                    MUL2(o2, acc[r], iv);
                    ((ull*)out)[(size_t)qg * 32 + lane] = o2;
                } else {
                    const int slot = mkr[r] - 1;         // 1->0, 2->1
                    float* pacc = g_acc + ((size_t)slot * NQG + qg) * DK;
                    ((ull*)pacc)[lane] = acc[r];
                    if (lane == 0) g_l[slot * NQG + qg] = lv[r];
                    __syncwarp();                        // all payload stores before release
                    unsigned old = 0;
                    if (lane == 0)
                        asm volatile("atom.acq_rel.gpu.global.add.u32 %0, [%1], %2;"
                                     : "=r"(old) : "l"(g_cnt + qg), "r"(1u) : "memory");
                    old = __shfl_sync(0xFFFFFFFFu, old, 0);   // sync distributes acquire
                    if (old == 1) {
                        const int ps = 1 - slot;
                        const float2 pp = __ldcg((const float2*)
                            (g_acc + ((size_t)ps * NQG + qg) * DK) + lane);
                        const float lp = __ldcg(g_l + ps * NQG + qg);
                        ull p2, s2, iv, o2;
                        PACK2(p2, pp.x, pp.y);
                        ADD2(s2, acc[r], p2);
                        DUP2(iv, 1.0f / (lv[r] + lp));
                        MUL2(o2, s2, iv);
                        ((ull*)out)[(size_t)qg * 32 + lane] = o2;
                        if (lane == 0) g_cnt[qg] = 0;    // reset for next replay
                    }
                }
            }
        }

        // ---- steal next unit ----
        if (tid == 0) *nextu = atomicAdd(&g_ticket, 1);
        __syncthreads();
        u = *nextu;
    }

    // ---- last CTA out resets the ticket for the next graph replay ----
    if (tid == 0) {
        __threadfence();
        int e = atomicAdd(&g_exit, 1);
        if (e == GRID_P - 1) { g_ticket = GRID_P; g_exit = 0; }
    }
}

// ---------------------------------------------------------------------------
extern "C" void kernel_launch(void* const* d_in, const int* in_sizes, int n_in,
                              void* d_out, int out_size)
{
    const float* q = nullptr; const float* k = nullptr; const float* v = nullptr;
    const int* idx = nullptr;
    for (int i = 0; i < n_in; i++) {
        const int s = in_sizes[i];
        if (s == HH * TQ * DK && !q)  q = (const float*)d_in[i];       // 1,048,576
        else if (s == HH * TT * DK) {                                   // 2,097,152
            if (!k) k = (const float*)d_in[i];
            else if (!v) v = (const float*)d_in[i];
        }
        else if (s == HH * TQ * 2)    idx = (const int*)d_in[i];        // 32,768
    }

    cudaFuncSetAttribute(partial_kernel,
                         cudaFuncAttributeMaxDynamicSharedMemorySize, SMEM_BYTES);
    partial_kernel<<<GRID_P, 256, SMEM_BYTES>>>(q, k, v, idx, (float*)d_out);
}

// round 8
// speedup vs baseline: 1.6753x; 1.6753x over previous
#include <cuda_runtime.h>
#include <cstddef>

#define HH   8
#define TQ   2048
#define TT   4096
#define DK   64
#define NB   64
#define NQG    (HH*TQ)     // 16384
#define NUNITS (HH*NB)     // 512
#define GRID_P 296         // 2 CTAs/SM x 148 SMs; all co-resident (spin-safe)

typedef unsigned long long ull;

// Per-slot flash partials, no max shift (scores O(1); exp fp32-safe, proven R4/R5):
//   g_acc[slot][q][64] unnormalized exp(s)·V ;  g_l2[q] = (l_slot0, l_slot1)
__device__ float  g_acc[2u * NQG * DK];
__device__ float2 g_l2[NQG];
__device__ int    g_ticket = GRID_P;
__device__ int    g_done   = 0;        // units fully stored+fenced
__device__ int    g_exit   = 0;

#define FMA2(d,a,b,c) asm("fma.rn.f32x2 %0, %1, %2, %3;" : "=l"(d) : "l"(a), "l"(b), "l"(c))
#define ADD2(d,a,b)   asm("add.rn.f32x2 %0, %1, %2;"     : "=l"(d) : "l"(a), "l"(b))
#define MUL2(d,a,b)   asm("mul.rn.f32x2 %0, %1, %2;"     : "=l"(d) : "l"(a), "l"(b))

// ---- dynamic SMEM layout (float offsets) ----
#define KS_OFF    0        // K block: 64 rows x 68 floats (conflict-free LDS.128)
#define VS_OFF    4352     // V block: same
#define UBUF_OFF  8704     // per-warp 1024 floats: phase1 q rows, phase2 dup'd P
#define QLIST_OFF 16896    // 2048 ushort
#define NM_OFF    17920    // nmatch, nextu
#define SMEM_BYTES ((NM_OFF + 2) * 4)   // 71688

__global__ __launch_bounds__(256, 2)
void partial_kernel(const float* __restrict__ q,
                    const float* __restrict__ k,
                    const float* __restrict__ v,
                    const int*   __restrict__ idx,
                    float*       __restrict__ out)
{
    extern __shared__ float sm[];
    float* ks = sm + KS_OFF;
    float* vs = sm + VS_OFF;
    unsigned short* qlist = (unsigned short*)(sm + QLIST_OFF);
    int* nmatch = (int*)(sm + NM_OFF);
    int* nextu  = nmatch + 1;

    const int tid  = threadIdx.x;
    const int warp = tid >> 5;
    const int lane = tid & 31;
    float* ubuf = sm + UBUF_OFF + warp * 1024;

    int u = blockIdx.x;
    while (u < NUNITS) {
        const int hh = u >> 6, bl = u & 63;
        if (tid == 0) *nmatch = 0;

        // ---- stage K/V block (64x64 f32) into padded SMEM ----
        const float4* kg = (const float4*)(k + ((size_t)hh * TT + (size_t)bl * 64) * DK);
        const float4* vg = (const float4*)(v + ((size_t)hh * TT + (size_t)bl * 64) * DK);
        float4* ks4 = (float4*)ks;
        float4* vs4 = (float4*)vs;
        #pragma unroll
        for (int i = tid; i < 1024; i += 256) {
            int row = i >> 4, c = i & 15;
            ks4[row * 17 + c] = kg[i];
            vs4[row * 17 + c] = vg[i];
        }
        __syncthreads();

        // ---- scan top2 list; warp-aggregated append ----
        const int2* idxh = (const int2*)(idx + (size_t)hh * TQ * 2);
        #pragma unroll
        for (int qq = tid; qq < TQ; qq += 256) {
            int2 t2 = idxh[qq];
            int mk = (t2.x == bl ? 1 : 0) | (t2.y == bl ? 2 : 0);
            unsigned bal = __ballot_sync(0xFFFFFFFFu, mk != 0);
            if (mk) {
                int leader = __ffs(bal) - 1;
                int base;
                if (lane == leader) base = atomicAdd(nmatch, __popc(bal));
                base = __shfl_sync(bal, base, leader);
                int pos = base + __popc(bal & ((1u << lane) - 1u));
                qlist[pos] = (unsigned short)(qq | (mk << 12));
            }
        }
        __syncthreads();
        const int n = *nmatch;

        // ---- warp-tiles of 8 queries ----
        for (int base = warp * 8; base < n; base += 64) {
            const int nt = min(8, n - base);
            int qgr[8], mkr[8];
            #pragma unroll
            for (int r = 0; r < 8; r++) {
                int e = base + ((r < nt) ? r : 0);
                unsigned short ent = qlist[e];
                qgr[r] = hh * TQ + (ent & 0x0FFF);
                mkr[r] = (r < nt) ? (ent >> 12) : 0;
            }

            __syncwarp();   // prior tile's ubuf reads done
            #pragma unroll
            for (int r = 0; r < 8; r++) {
                float2 qv = ((const float2*)(q + (size_t)qgr[r] * DK))[lane];
                ((float2*)(ubuf + r * 64))[lane] = qv;
            }
            __syncwarp();

            // ---- QK: lane owns keys {lane, lane+32}; f32x2 along dk ----
            ull sA[8], sB[8];
            #pragma unroll
            for (int r = 0; r < 8; r++) { sA[r] = 0ull; sB[r] = 0ull; }
            {
                const ulonglong2* ka4 = (const ulonglong2*)(ks + lane * 68);
                const ulonglong2* kb4 = (const ulonglong2*)(ks + (lane + 32) * 68);
                #pragma unroll
                for (int i = 0; i < 16; i++) {
                    ulonglong2 ka = ka4[i];
                    ulonglong2 kb = kb4[i];
                    #pragma unroll
                    for (int r = 0; r < 8; r++) {
                        ulonglong2 qv = ((const ulonglong2*)(ubuf + r * 64))[i];
                        FMA2(sA[r], qv.x, ka.x, sA[r]);
                        FMA2(sA[r], qv.y, ka.y, sA[r]);
                        FMA2(sB[r], qv.x, kb.x, sB[r]);
                        FMA2(sB[r], qv.y, kb.y, sB[r]);
                    }
                }
            }
            __syncwarp();   // q reads done before P overwrites ubuf

            // ---- exp + l reduction; store P duplicated (p,p) ----
            float lv[8];
            #pragma unroll
            for (int r = 0; r < 8; r++) {
                unsigned lo, hi;
                asm("mov.b64 {%0,%1}, %2;" : "=r"(lo), "=r"(hi) : "l"(sA[r]));
                float s0 = (__uint_as_float(lo) + __uint_as_float(hi)) * 0.125f;
                asm("mov.b64 {%0,%1}, %2;" : "=r"(lo), "=r"(hi) : "l"(sB[r]));
                float s1 = (__uint_as_float(lo) + __uint_as_float(hi)) * 0.125f;
                float e0 = __expf(s0), e1 = __expf(s1);
                float l = e0 + e1;
                #pragma unroll
                for (int o = 16; o; o >>= 1) l += __shfl_xor_sync(0xFFFFFFFFu, l, o);
                ull d0, d1;
                asm("mov.b64 %0, {%1,%1};" : "=l"(d0) : "r"(__float_as_uint(e0)));
                asm("mov.b64 %0, {%1,%1};" : "=l"(d1) : "r"(__float_as_uint(e1)));
                ((ull*)ubuf)[r * 64 + lane]      = d0;   // key = lane
                ((ull*)ubuf)[r * 64 + lane + 32] = d1;   // key = lane+32
                lv[r] = l;
            }
            __syncwarp();

            // ---- PV: lane owns dims {2l,2l+1}; LDS.128 reads 2 keys of P ----
            ull acc[8];
            #pragma unroll
            for (int r = 0; r < 8; r++) acc[r] = 0ull;
            {
                const ull* vr = (const ull*)vs;                  // row j at 34*j
                const ulonglong2* pb2 = (const ulonglong2*)ubuf; // [r*32+jj] = keys 2jj,2jj+1
                #pragma unroll 4
                for (int jj = 0; jj < 32; jj++) {
                    ull v2a = vr[(2 * jj)     * 34 + lane];
                    ull v2b = vr[(2 * jj + 1) * 34 + lane];
                    #pragma unroll
                    for (int r = 0; r < 8; r++) {
                        ulonglong2 p2 = pb2[r * 32 + jj];        // broadcast
                        FMA2(acc[r], p2.x, v2a, acc[r]);
                        FMA2(acc[r], p2.y, v2b, acc[r]);
                    }
                }
            }

            // ---- write partials; dup (mk==3) fills both slots ----
            #pragma unroll
            for (int r = 0; r < 8; r++) {
                if (mkr[r] & 1) {
                    ((ull*)(g_acc + (size_t)qgr[r] * DK))[lane] = acc[r];
                    if (lane == 0) g_l2[qgr[r]].x = lv[r];
                }
                if (mkr[r] & 2) {
                    ((ull*)(g_acc + ((size_t)NQG + qgr[r]) * DK))[lane] = acc[r];
                    if (lane == 0) g_l2[qgr[r]].y = lv[r];
                }
            }
        }

        // ---- release this unit's stores, count it done, steal next ----
        __threadfence();                 // all threads: order STGs before g_done
        __syncthreads();
        if (tid == 0) {
            atomicAdd(&g_done, 1);
            *nextu = atomicAdd(&g_ticket, 1);
        }
        __syncthreads();
        u = *nextu;
    }

    // ================= fused combine =================
    if (tid == 0) {
        int d;
        do {
            asm volatile("ld.acquire.gpu.global.s32 %0, [%1];"
                         : "=r"(d) : "l"(&g_done));
        } while (d < NUNITS);
    }
    __syncthreads();   // acquire by tid0 + barrier; data addrs never in our L1

    for (int i = blockIdx.x * 256 + tid; i < NQG * 16; i += GRID_P * 256) {
        const int qg = i >> 4;
        const float2 ll = __ldcg(&g_l2[qg]);
        const float4 a  = __ldcg((const float4*)g_acc + i);
        const float4 b  = __ldcg((const float4*)g_acc + (NQG * 16) + i);
        const float inv = 1.0f / (ll.x + ll.y);
        float4 o;
        o.x = (a.x + b.x) * inv;
        o.y = (a.y + b.y) * inv;
        o.z = (a.z + b.z) * inv;
        o.w = (a.w + b.w) * inv;
        ((float4*)out)[i] = o;
    }

    // ---- last CTA resets scheduler state for the next graph replay ----
    if (tid == 0) {
        int e = atomicAdd(&g_exit, 1);
        if (e == GRID_P - 1) { g_ticket = GRID_P; g_done = 0; g_exit = 0; }
    }
}

// ---------------------------------------------------------------------------
extern "C" void kernel_launch(void* const* d_in, const int* in_sizes, int n_in,
                              void* d_out, int out_size)
{
    const float* q = nullptr; const float* k = nullptr; const float* v = nullptr;
    const int* idx = nullptr;
    for (int i = 0; i < n_in; i++) {
        const int s = in_sizes[i];
        if (s == HH * TQ * DK && !q)  q = (const float*)d_in[i];       // 1,048,576
        else if (s == HH * TT * DK) {                                   // 2,097,152
            if (!k) k = (const float*)d_in[i];
            else if (!v) v = (const float*)d_in[i];
        }
        else if (s == HH * TQ * 2)    idx = (const int*)d_in[i];        // 32,768
    }

    cudaFuncSetAttribute(partial_kernel,
                         cudaFuncAttributeMaxDynamicSharedMemorySize, SMEM_BYTES);
    partial_kernel<<<GRID_P, 256, SMEM_BYTES>>>(q, k, v, idx, (float*)d_out);
}

// round 11
// speedup vs baseline: 2.1726x; 1.2968x over previous
#include <cuda_runtime.h>
#include <cuda_bf16.h>
#include <cstdint>
#include <cstddef>

#define HH   8
#define TQ   2048
#define TT   4096
#define DK   64
#define NB   64
#define NQG    (HH*TQ)     // 16384
#define NUNITS (HH*NB)     // 512

typedef unsigned long long ull;

// Flash partials (no max shift: scores O(1), exp fp32-safe — proven R3..R7):
__device__ float  g_acc[2u * NQG * DK];
__device__ float2 g_l2[NQG];

// bf16 hi/lo split of two floats -> packed bf16x2 (lower half = x, upper = y)
__device__ __forceinline__ void split2(float x, float y, uint32_t& hi, uint32_t& lo) {
    uint32_t h;
    asm("cvt.rn.bf16x2.f32 %0, %1, %2;" : "=r"(h) : "f"(y), "f"(x));
    float xr = x - __uint_as_float(h << 16);
    float yr = y - __uint_as_float(h & 0xFFFF0000u);
    asm("cvt.rn.bf16x2.f32 %0, %1, %2;" : "=r"(lo) : "f"(yr), "f"(xr));
    hi = h;
}

#define MMA(c0,c1,c2,c3, a0,a1,a2,a3, b0,b1)                                  \
    asm volatile("mma.sync.aligned.m16n8k16.row.col.f32.bf16.bf16.f32 "       \
        "{%0,%1,%2,%3}, {%4,%5,%6,%7}, {%8,%9}, {%0,%1,%2,%3};"               \
        : "+f"(c0), "+f"(c1), "+f"(c2), "+f"(c3)                              \
        : "r"(a0), "r"(a1), "r"(a2), "r"(a3), "r"(b0), "r"(b1))

// SMEM row strides (bytes): chosen so B-fragment LDS.32 is conflict-free:
//   K rows 144B  -> bank(lane) = 4*gid + t  (all 32 distinct)
//   VT rows 148B -> staging STS conflict-free (5*lane+j), LDS ~1.06-way
#define KPITCH  144
#define VPITCH  148

__global__ __launch_bounds__(64)
void partial_kernel(const float* __restrict__ q,
                    const float* __restrict__ k,
                    const float* __restrict__ v,
                    const int*   __restrict__ idx)
{
    __shared__ char khi[64 * KPITCH];
    __shared__ char klo[64 * KPITCH];
    __shared__ char vthi[64 * VPITCH];   // V^T: row = dim d, 64 keys bf16
    __shared__ char vtlo[64 * VPITCH];
    __shared__ unsigned short qlist[TQ];
    __shared__ int nmatch;

    const int tid  = threadIdx.x;
    const int warp = tid >> 5;
    const int lane = tid & 31;
    const int gid  = lane >> 2;          // mma group id (row)
    const int tig  = lane & 3;           // thread-in-group (col pair)

    const int u  = blockIdx.x;
    const int hh = u >> 6, bl = u & 63;
    if (tid == 0) nmatch = 0;

    // ---- stage K (bf16 hi/lo, [key][dk], 144B pitch) ----
    {
        const float4* kg = (const float4*)(k + ((size_t)hh * TT + (size_t)bl * 64) * DK);
        for (int i = tid; i < 1024; i += 64) {
            float4 x = kg[i];
            int row = i >> 4, c = i & 15;           // dims 4c..4c+3
            uint32_t h01, l01, h23, l23;
            split2(x.x, x.y, h01, l01);
            split2(x.z, x.w, h23, l23);
            *(uint2*)(khi + row * KPITCH + c * 8) = make_uint2(h01, h23);
            *(uint2*)(klo + row * KPITCH + c * 8) = make_uint2(l01, l23);
        }
    }
    // ---- stage V^T (bf16 hi/lo, [dim][key], 148B pitch) ----
    {
        const float* vg = v + ((size_t)hh * TT + (size_t)bl * 64) * DK;
        const int d = tid;                          // 64 threads = 64 dims
        #pragma unroll 4
        for (int j = 0; j < 32; j++) {
            float a = vg[(size_t)(2 * j)     * DK + d];
            float b = vg[(size_t)(2 * j + 1) * DK + d];
            uint32_t hi, lo;
            split2(a, b, hi, lo);
            *(uint32_t*)(vthi + d * VPITCH + j * 4) = hi;
            *(uint32_t*)(vtlo + d * VPITCH + j * 4) = lo;
        }
    }
    // ---- scan this head's top2 list; warp-aggregated append ----
    {
        const int2* idxh = (const int2*)(idx + (size_t)hh * TQ * 2);
        for (int qq = tid; qq < TQ; qq += 64) {
            int2 t2 = idxh[qq];
            int mk = (t2.x == bl ? 1 : 0) | (t2.y == bl ? 2 : 0);
            unsigned bal = __ballot_sync(0xFFFFFFFFu, mk != 0);
            if (mk) {
                int leader = __ffs(bal) - 1;
                int basep;
                if (lane == leader) basep = atomicAdd(&nmatch, __popc(bal));
                basep = __shfl_sync(bal, basep, leader);
                qlist[basep + __popc(bal & ((1u << lane) - 1u))] =
                    (unsigned short)(qq | (mk << 12));
            }
        }
    }
    __syncthreads();
    const int n = nmatch;

    // ---- 16-query warp tiles (warp owns rows base..base+15) ----
    for (int base = warp * 16; base < n; base += 32) {
        // rows this thread touches: gid and gid+8
        const int e0 = base + gid, e1 = base + gid + 8;
        const unsigned short w0 = qlist[(e0 < n) ? e0 : 0];
        const unsigned short w1 = qlist[(e1 < n) ? e1 : 0];
        const int qg0 = hh * TQ + (w0 & 0x0FFF);
        const int qg1 = hh * TQ + (w1 & 0x0FFF);
        const int mk0 = (e0 < n) ? (w0 >> 12) : 0;
        const int mk1 = (e1 < n) ? (w1 >> 12) : 0;
        const float* qr0 = q + (size_t)qg0 * DK;
        const float* qr1 = q + (size_t)qg1 * DK;

        // ---- QK: S[16,64] = Q·K^T via 3-term bf16 split ----
        float sc[8][4];
        #pragma unroll
        for (int nt = 0; nt < 8; nt++)
            sc[nt][0] = sc[nt][1] = sc[nt][2] = sc[nt][3] = 0.f;

        #pragma unroll
        for (int kc = 0; kc < 4; kc++) {
            // A fragment (Q) hi/lo for chunk kc
            uint32_t ah[4], al[4];
            {
                float2 x0 = *(const float2*)(qr0 + kc * 16 + 2 * tig);
                float2 x1 = *(const float2*)(qr1 + kc * 16 + 2 * tig);
                float2 x2 = *(const float2*)(qr0 + kc * 16 + 2 * tig + 8);
                float2 x3 = *(const float2*)(qr1 + kc * 16 + 2 * tig + 8);
                split2(x0.x, x0.y, ah[0], al[0]);
                split2(x1.x, x1.y, ah[1], al[1]);
                split2(x2.x, x2.y, ah[2], al[2]);
                split2(x3.x, x3.y, ah[3], al[3]);
            }
            #pragma unroll
            for (int nt = 0; nt < 8; nt++) {
                const char* kb = khi + (nt * 8 + gid) * KPITCH + kc * 32 + tig * 4;
                const char* lb = klo + (nt * 8 + gid) * KPITCH + kc * 32 + tig * 4;
                uint32_t bh0 = *(const uint32_t*)(kb);
                uint32_t bh1 = *(const uint32_t*)(kb + 16);
                uint32_t bl0 = *(const uint32_t*)(lb);
                uint32_t bl1 = *(const uint32_t*)(lb + 16);
                MMA(sc[nt][0], sc[nt][1], sc[nt][2], sc[nt][3],
                    ah[0], ah[1], ah[2], ah[3], bh0, bh1);     // Qhi·Khi
                MMA(sc[nt][0], sc[nt][1], sc[nt][2], sc[nt][3],
                    al[0], al[1], al[2], al[3], bh0, bh1);     // Qlo·Khi
                MMA(sc[nt][0], sc[nt][1], sc[nt][2], sc[nt][3],
                    ah[0], ah[1], ah[2], ah[3], bl0, bl1);     // Qhi·Klo
            }
        }

        // ---- softmax partials: p = exp(s/8); l row-sums; P -> bf16 hi/lo ----
        uint32_t phi0[8], phi1[8], plo0[8], plo1[8];
        float sum0 = 0.f, sum1 = 0.f;
        #pragma unroll
        for (int nt = 0; nt < 8; nt++) {
            float p0 = __expf(sc[nt][0] * 0.125f);
            float p1 = __expf(sc[nt][1] * 0.125f);
            float p2 = __expf(sc[nt][2] * 0.125f);
            float p3 = __expf(sc[nt][3] * 0.125f);
            sum0 += p0 + p1;
            sum1 += p2 + p3;
            split2(p0, p1, phi0[nt], plo0[nt]);   // row gid
            split2(p2, p3, phi1[nt], plo1[nt]);   // row gid+8
        }
        sum0 += __shfl_xor_sync(0xFFFFFFFFu, sum0, 1);
        sum0 += __shfl_xor_sync(0xFFFFFFFFu, sum0, 2);
        sum1 += __shfl_xor_sync(0xFFFFFFFFu, sum1, 1);
        sum1 += __shfl_xor_sync(0xFFFFFFFFu, sum1, 2);

        // ---- PV: O[16,64] = P·V via 3-term split; C frags accumulate ----
        float oc[8][4];
        #pragma unroll
        for (int nt = 0; nt < 8; nt++)
            oc[nt][0] = oc[nt][1] = oc[nt][2] = oc[nt][3] = 0.f;

        #pragma unroll
        for (int kc = 0; kc < 4; kc++) {
            // A fragment (P) chunk kc = S n-tiles 2kc, 2kc+1 (direct mapping)
            const uint32_t pah0 = phi0[2 * kc],     pah1 = phi1[2 * kc];
            const uint32_t pah2 = phi0[2 * kc + 1], pah3 = phi1[2 * kc + 1];
            const uint32_t pal0 = plo0[2 * kc],     pal1 = plo1[2 * kc];
            const uint32_t pal2 = plo0[2 * kc + 1], pal3 = plo1[2 * kc + 1];
            #pragma unroll
            for (int nt = 0; nt < 8; nt++) {
                const char* vb = vthi + (nt * 8 + gid) * VPITCH + kc * 32 + tig * 4;
                const char* wb = vtlo + (nt * 8 + gid) * VPITCH + kc * 32 + tig * 4;
                uint32_t bh0 = *(const uint32_t*)(vb);
                uint32_t bh1 = *(const uint32_t*)(vb + 16);
                uint32_t bl0 = *(const uint32_t*)(wb);
                uint32_t bl1 = *(const uint32_t*)(wb + 16);
                MMA(oc[nt][0], oc[nt][1], oc[nt][2], oc[nt][3],
                    pah0, pah1, pah2, pah3, bh0, bh1);         // Phi·Vhi
                MMA(oc[nt][0], oc[nt][1], oc[nt][2], oc[nt][3],
                    pal0, pal1, pal2, pal3, bh0, bh1);         // Plo·Vhi
                MMA(oc[nt][0], oc[nt][1], oc[nt][2], oc[nt][3],
                    pah0, pah1, pah2, pah3, bl0, bl1);         // Phi·Vlo
            }
        }

        // ---- store flash partials (unnormalized; dup mk==3 fills both) ----
        #pragma unroll
        for (int slot = 0; slot < 2; slot++) {
            const size_t sbase = (size_t)slot * NQG * DK;
            if (mk0 & (1 << slot)) {
                #pragma unroll
                for (int nt = 0; nt < 8; nt++)
                    *(float2*)(g_acc + sbase + (size_t)qg0 * DK + nt * 8 + 2 * tig) =
                        make_float2(oc[nt][0], oc[nt][1]);
                if (tig == 0) {
                    if (slot == 0) g_l2[qg0].x = sum0; else g_l2[qg0].y = sum0;
                }
            }
            if (mk1 & (1 << slot)) {
                #pragma unroll
                for (int nt = 0; nt < 8; nt++)
                    *(float2*)(g_acc + sbase + (size_t)qg1 * DK + nt * 8 + 2 * tig) =
                        make_float2(oc[nt][2], oc[nt][3]);
                if (tig == 0) {
                    if (slot == 0) g_l2[qg1].x = sum1; else g_l2[qg1].y = sum1;
                }
            }
        }
    }
}

// ---------------------------------------------------------------------------
// Combine: out = (acc0 + acc1) / (l0 + l1).
// ---------------------------------------------------------------------------
__global__ __launch_bounds__(256)
void combine_kernel(float* __restrict__ out)
{
    const int t  = blockIdx.x * 256 + threadIdx.x;
    const int qg = t >> 4;
    const float2 ll = g_l2[qg];
    const float4 a  = ((const float4*)g_acc)[t];
    const float4 b  = ((const float4*)g_acc)[NQG * 16 + t];
    const float inv = 1.0f / (ll.x + ll.y);
    float4 o;
    o.x = (a.x + b.x) * inv;
    o.y = (a.y + b.y) * inv;
    o.z = (a.z + b.z) * inv;
    o.w = (a.w + b.w) * inv;
    ((float4*)out)[t] = o;
}

// ---------------------------------------------------------------------------
extern "C" void kernel_launch(void* const* d_in, const int* in_sizes, int n_in,
                              void* d_out, int out_size)
{
    const float* q = nullptr; const float* k = nullptr; const float* v = nullptr;
    const int* idx = nullptr;
    for (int i = 0; i < n_in; i++) {
        const int s = in_sizes[i];
        if (s == HH * TQ * DK && !q)  q = (const float*)d_in[i];       // 1,048,576
        else if (s == HH * TT * DK) {                                   // 2,097,152
            if (!k) k = (const float*)d_in[i];
            else if (!v) v = (const float*)d_in[i];
        }
        else if (s == HH * TQ * 2)    idx = (const int*)d_in[i];        // 32,768
    }

    partial_kernel<<<NUNITS, 64>>>(q, k, v, idx);
    combine_kernel<<<(NQG * 16) / 256, 256>>>((float*)d_out);
}

// round 12
// speedup vs baseline: 2.8707x; 1.3213x over previous
#include <cuda_runtime.h>
#include <cuda_bf16.h>
#include <cstdint>
#include <cstddef>

#define HH   8
#define TQ   2048
#define TT   4096
#define DK   64
#define NB   64
#define NQG    (HH*TQ)     // 16384
#define NUNITS (HH*NB)     // 512

typedef unsigned long long ull;

// Flash partials (no max shift: scores O(1), exp fp32-safe — proven R3..R10):
__device__ float  g_acc[2u * NQG * DK];
__device__ float2 g_l2[NQG];

// bf16 hi/lo split of two floats -> packed bf16x2 (lower half = x, upper = y)
__device__ __forceinline__ void split2(float x, float y, uint32_t& hi, uint32_t& lo) {
    uint32_t h;
    asm("cvt.rn.bf16x2.f32 %0, %1, %2;" : "=r"(h) : "f"(y), "f"(x));
    float xr = x - __uint_as_float(h << 16);
    float yr = y - __uint_as_float(h & 0xFFFF0000u);
    asm("cvt.rn.bf16x2.f32 %0, %1, %2;" : "=r"(lo) : "f"(yr), "f"(xr));
    hi = h;
}

#define MMA(c0,c1,c2,c3, a0,a1,a2,a3, b0,b1)                                  \
    asm volatile("mma.sync.aligned.m16n8k16.row.col.f32.bf16.bf16.f32 "       \
        "{%0,%1,%2,%3}, {%4,%5,%6,%7}, {%8,%9}, {%0,%1,%2,%3};"               \
        : "+f"(c0), "+f"(c1), "+f"(c2), "+f"(c3)                              \
        : "r"(a0), "r"(a1), "r"(a2), "r"(a3), "r"(b0), "r"(b1))

// SMEM row strides (bytes): chosen so B-fragment LDS.32 is conflict-free:
//   K rows 144B  -> bank(lane) = 4*gid + t  (all 32 distinct)
//   VT rows 148B -> staging STS conflict-free, LDS ~1.06-way
#define KPITCH  144
#define VPITCH  148

__global__ __launch_bounds__(128, 3)
void partial_kernel(const float* __restrict__ q,
                    const float* __restrict__ k,
                    const float* __restrict__ v,
                    const int*   __restrict__ idx)
{
    __shared__ char khi[64 * KPITCH];
    __shared__ char klo[64 * KPITCH];
    __shared__ char vthi[64 * VPITCH];   // V^T: row = dim d, 64 keys bf16
    __shared__ char vtlo[64 * VPITCH];
    __shared__ unsigned short qlist[TQ];
    __shared__ int nmatch;

    const int tid  = threadIdx.x;
    const int warp = tid >> 5;           // 0..3
    const int lane = tid & 31;
    const int gid  = lane >> 2;          // mma group id (row)
    const int tig  = lane & 3;           // thread-in-group (col pair)

    const int u  = blockIdx.x;
    const int hh = u >> 6, bl = u & 63;
    if (tid == 0) nmatch = 0;

    // ---- stage K (bf16 hi/lo, [key][dk], 144B pitch) ----
    {
        const float4* kg = (const float4*)(k + ((size_t)hh * TT + (size_t)bl * 64) * DK);
        #pragma unroll 2
        for (int i = tid; i < 1024; i += 128) {
            float4 x = kg[i];
            int row = i >> 4, c = i & 15;           // dims 4c..4c+3
            uint32_t h01, l01, h23, l23;
            split2(x.x, x.y, h01, l01);
            split2(x.z, x.w, h23, l23);
            *(uint2*)(khi + row * KPITCH + c * 8) = make_uint2(h01, h23);
            *(uint2*)(klo + row * KPITCH + c * 8) = make_uint2(l01, l23);
        }
    }
    // ---- stage V^T (bf16 hi/lo, [dim][key], 148B pitch) ----
    {
        const float* vg = v + ((size_t)hh * TT + (size_t)bl * 64) * DK;
        const int d  = tid & 63;
        const int jh = (tid >> 6) * 16;             // j-pairs [jh, jh+16)
        #pragma unroll 4
        for (int jj = 0; jj < 16; jj++) {
            const int j = jh + jj;
            float a = vg[(size_t)(2 * j)     * DK + d];
            float b = vg[(size_t)(2 * j + 1) * DK + d];
            uint32_t hi, lo;
            split2(a, b, hi, lo);
            *(uint32_t*)(vthi + d * VPITCH + j * 4) = hi;
            *(uint32_t*)(vtlo + d * VPITCH + j * 4) = lo;
        }
    }
    // ---- scan this head's top2 list; warp-aggregated append ----
    {
        const int2* idxh = (const int2*)(idx + (size_t)hh * TQ * 2);
        #pragma unroll 4
        for (int qq = tid; qq < TQ; qq += 128) {
            int2 t2 = idxh[qq];
            int mk = (t2.x == bl ? 1 : 0) | (t2.y == bl ? 2 : 0);
            unsigned bal = __ballot_sync(0xFFFFFFFFu, mk != 0);
            if (mk) {
                int leader = __ffs(bal) - 1;
                int basep;
                if (lane == leader) basep = atomicAdd(&nmatch, __popc(bal));
                basep = __shfl_sync(bal, basep, leader);
                qlist[basep + __popc(bal & ((1u << lane) - 1u))] =
                    (unsigned short)(qq | (mk << 12));
            }
        }
    }
    __syncthreads();
    const int n = nmatch;

    // ---- 16-query warp tiles; 4 warps stride the tile list ----
    for (int base = warp * 16; base < n; base += 64) {
        // rows this thread touches: gid and gid+8
        const int e0 = base + gid, e1 = base + gid + 8;
        const unsigned short w0 = qlist[(e0 < n) ? e0 : 0];
        const unsigned short w1 = qlist[(e1 < n) ? e1 : 0];
        const int qg0 = hh * TQ + (w0 & 0x0FFF);
        const int qg1 = hh * TQ + (w1 & 0x0FFF);
        const int mk0 = (e0 < n) ? (w0 >> 12) : 0;
        const int mk1 = (e1 < n) ? (w1 >> 12) : 0;
        const float* qr0 = q + (size_t)qg0 * DK;
        const float* qr1 = q + (size_t)qg1 * DK;

        // ---- QK: S[16,64] = Q·K^T via 3-term bf16 split ----
        float sc[8][4];
        #pragma unroll
        for (int nt = 0; nt < 8; nt++)
            sc[nt][0] = sc[nt][1] = sc[nt][2] = sc[nt][3] = 0.f;

        #pragma unroll
        for (int kc = 0; kc < 4; kc++) {
            uint32_t ah[4], al[4];
            {
                float2 x0 = *(const float2*)(qr0 + kc * 16 + 2 * tig);
                float2 x1 = *(const float2*)(qr1 + kc * 16 + 2 * tig);
                float2 x2 = *(const float2*)(qr0 + kc * 16 + 2 * tig + 8);
                float2 x3 = *(const float2*)(qr1 + kc * 16 + 2 * tig + 8);
                split2(x0.x, x0.y, ah[0], al[0]);
                split2(x1.x, x1.y, ah[1], al[1]);
                split2(x2.x, x2.y, ah[2], al[2]);
                split2(x3.x, x3.y, ah[3], al[3]);
            }
            #pragma unroll
            for (int nt = 0; nt < 8; nt++) {
                const char* kb = khi + (nt * 8 + gid) * KPITCH + kc * 32 + tig * 4;
                const char* lb = klo + (nt * 8 + gid) * KPITCH + kc * 32 + tig * 4;
                uint32_t bh0 = *(const uint32_t*)(kb);
                uint32_t bh1 = *(const uint32_t*)(kb + 16);
                uint32_t bl0 = *(const uint32_t*)(lb);
                uint32_t bl1 = *(const uint32_t*)(lb + 16);
                MMA(sc[nt][0], sc[nt][1], sc[nt][2], sc[nt][3],
                    ah[0], ah[1], ah[2], ah[3], bh0, bh1);     // Qhi·Khi
                MMA(sc[nt][0], sc[nt][1], sc[nt][2], sc[nt][3],
                    al[0], al[1], al[2], al[3], bh0, bh1);     // Qlo·Khi
                MMA(sc[nt][0], sc[nt][1], sc[nt][2], sc[nt][3],
                    ah[0], ah[1], ah[2], ah[3], bl0, bl1);     // Qhi·Klo
            }
        }

        // ---- softmax partials: p = exp(s/8); l row-sums; P -> bf16 hi/lo ----
        uint32_t phi0[8], phi1[8], plo0[8], plo1[8];
        float sum0 = 0.f, sum1 = 0.f;
        #pragma unroll
        for (int nt = 0; nt < 8; nt++) {
            float p0 = __expf(sc[nt][0] * 0.125f);
            float p1 = __expf(sc[nt][1] * 0.125f);
            float p2 = __expf(sc[nt][2] * 0.125f);
            float p3 = __expf(sc[nt][3] * 0.125f);
            sum0 += p0 + p1;
            sum1 += p2 + p3;
            split2(p0, p1, phi0[nt], plo0[nt]);   // row gid
            split2(p2, p3, phi1[nt], plo1[nt]);   // row gid+8
        }
        sum0 += __shfl_xor_sync(0xFFFFFFFFu, sum0, 1);
        sum0 += __shfl_xor_sync(0xFFFFFFFFu, sum0, 2);
        sum1 += __shfl_xor_sync(0xFFFFFFFFu, sum1, 1);
        sum1 += __shfl_xor_sync(0xFFFFFFFFu, sum1, 2);

        // ---- PV: O[16,64] = P·V via 3-term split ----
        float oc[8][4];
        #pragma unroll
        for (int nt = 0; nt < 8; nt++)
            oc[nt][0] = oc[nt][1] = oc[nt][2] = oc[nt][3] = 0.f;

        #pragma unroll
        for (int kc = 0; kc < 4; kc++) {
            // A fragment (P) chunk kc = S n-tiles 2kc, 2kc+1 (direct mapping)
            const uint32_t pah0 = phi0[2 * kc],     pah1 = phi1[2 * kc];
            const uint32_t pah2 = phi0[2 * kc + 1], pah3 = phi1[2 * kc + 1];
            const uint32_t pal0 = plo0[2 * kc],     pal1 = plo1[2 * kc];
            const uint32_t pal2 = plo0[2 * kc + 1], pal3 = plo1[2 * kc + 1];
            #pragma unroll
            for (int nt = 0; nt < 8; nt++) {
                const char* vb = vthi + (nt * 8 + gid) * VPITCH + kc * 32 + tig * 4;
                const char* wb = vtlo + (nt * 8 + gid) * VPITCH + kc * 32 + tig * 4;
                uint32_t bh0 = *(const uint32_t*)(vb);
                uint32_t bh1 = *(const uint32_t*)(vb + 16);
                uint32_t bl0 = *(const uint32_t*)(wb);
                uint32_t bl1 = *(const uint32_t*)(wb + 16);
                MMA(oc[nt][0], oc[nt][1], oc[nt][2], oc[nt][3],
                    pah0, pah1, pah2, pah3, bh0, bh1);         // Phi·Vhi
                MMA(oc[nt][0], oc[nt][1], oc[nt][2], oc[nt][3],
                    pal0, pal1, pal2, pal3, bh0, bh1);         // Plo·Vhi
                MMA(oc[nt][0], oc[nt][1], oc[nt][2], oc[nt][3],
                    pah0, pah1, pah2, pah3, bl0, bl1);         // Phi·Vlo
            }
        }

        // ---- store flash partials (unnormalized; dup mk==3 fills both) ----
        #pragma unroll
        for (int slot = 0; slot < 2; slot++) {
            const size_t sbase = (size_t)slot * NQG * DK;
            if (mk0 & (1 << slot)) {
                #pragma unroll
                for (int nt = 0; nt < 8; nt++)
                    *(float2*)(g_acc + sbase + (size_t)qg0 * DK + nt * 8 + 2 * tig) =
                        make_float2(oc[nt][0], oc[nt][1]);
                if (tig == 0) {
                    if (slot == 0) g_l2[qg0].x = sum0; else g_l2[qg0].y = sum0;
                }
            }
            if (mk1 & (1 << slot)) {
                #pragma unroll
                for (int nt = 0; nt < 8; nt++)
                    *(float2*)(g_acc + sbase + (size_t)qg1 * DK + nt * 8 + 2 * tig) =
                        make_float2(oc[nt][2], oc[nt][3]);
                if (tig == 0) {
                    if (slot == 0) g_l2[qg1].x = sum1; else g_l2[qg1].y = sum1;
                }
            }
        }
    }
}

// ---------------------------------------------------------------------------
// Combine: out = (acc0 + acc1) / (l0 + l1). 4 float4 per thread (ILP).
// ---------------------------------------------------------------------------
__global__ __launch_bounds__(256)
void combine_kernel(float* __restrict__ out)
{
    #pragma unroll
    for (int it = 0; it < 4; it++) {
        const int t  = it * (256 * 256) + blockIdx.x * 256 + threadIdx.x;
        const int qg = t >> 4;
        const float2 ll = g_l2[qg];
        const float4 a  = ((const float4*)g_acc)[t];
        const float4 b  = ((const float4*)g_acc)[NQG * 16 + t];
        const float inv = 1.0f / (ll.x + ll.y);
        float4 o;
        o.x = (a.x + b.x) * inv;
        o.y = (a.y + b.y) * inv;
        o.z = (a.z + b.z) * inv;
        o.w = (a.w + b.w) * inv;
        ((float4*)out)[t] = o;
    }
}

// ---------------------------------------------------------------------------
extern "C" void kernel_launch(void* const* d_in, const int* in_sizes, int n_in,
                              void* d_out, int out_size)
{
    const float* q = nullptr; const float* k = nullptr; const float* v = nullptr;
    const int* idx = nullptr;
    for (int i = 0; i < n_in; i++) {
        const int s = in_sizes[i];
        if (s == HH * TQ * DK && !q)  q = (const float*)d_in[i];       // 1,048,576
        else if (s == HH * TT * DK) {                                   // 2,097,152
            if (!k) k = (const float*)d_in[i];
            else if (!v) v = (const float*)d_in[i];
        }
        else if (s == HH * TQ * 2)    idx = (const int*)d_in[i];        // 32,768
    }

    partial_kernel<<<NUNITS, 128>>>(q, k, v, idx);
    combine_kernel<<<256, 256>>>((float*)d_out);
}